// round 1
// baseline (speedup 1.0000x reference)
#include <cuda_runtime.h>
#include <cuda_bf16.h>
#include <math.h>

// Problem shape (fixed by setup_inputs)
#define N     2048
#define C     256
#define NCLS  8
#define KSEL  20
#define MAXC  512      // safe upper bound on class size (binomial mean 256, sigma ~15)
#define EPS   1e-6f

// Scratch (static __device__ — no allocations)
__device__ float g_D[(size_t)N * MAXC];   // 4 MB: per-row distances to same-class members
__device__ int   g_order[N];
__device__ int   g_start[NCLS];
__device__ int   g_cnt[NCLS];
__device__ float g_rowloss[N];

__device__ __forceinline__ float finf() { return __int_as_float(0x7f800000); }

// ---------------------------------------------------------------------------
// Kernel 1: stable permutation grouping rows by class. One block, 256 threads,
// 8 rows per thread. Deterministic (scan-based, no atomics).
// ---------------------------------------------------------------------------
__global__ __launch_bounds__(256, 1)
void perm_kernel(const int* __restrict__ target) {
    __shared__ int sc[256][NCLS];
    int t = threadIdx.x;

    int tg[8];
    int loc[NCLS];
#pragma unroll
    for (int c = 0; c < NCLS; c++) loc[c] = 0;
#pragma unroll
    for (int u = 0; u < 8; u++) {
        tg[u] = target[t * 8 + u];
        loc[tg[u]]++;
    }
#pragma unroll
    for (int c = 0; c < NCLS; c++) sc[t][c] = loc[c];
    __syncthreads();

    // Hillis-Steele inclusive scan over 256 threads, vector of 8 counters
    for (int ofs = 1; ofs < 256; ofs <<= 1) {
        int add[NCLS];
        if (t >= ofs) {
#pragma unroll
            for (int c = 0; c < NCLS; c++) add[c] = sc[t - ofs][c];
        }
        __syncthreads();
        if (t >= ofs) {
#pragma unroll
            for (int c = 0; c < NCLS; c++) sc[t][c] += add[c];
        }
        __syncthreads();
    }

    __shared__ int start_s[NCLS];
    if (t == 0) {
        int acc = 0;
#pragma unroll
        for (int c = 0; c < NCLS; c++) {
            start_s[c] = acc;
            g_start[c] = acc;
            g_cnt[c]   = sc[255][c];
            acc += sc[255][c];
        }
    }
    __syncthreads();

    int off[NCLS];
#pragma unroll
    for (int c = 0; c < NCLS; c++) off[c] = sc[t][c] - loc[c];  // exclusive prefix
#pragma unroll
    for (int u = 0; u < 8; u++) {
        int c = tg[u];
        g_order[start_s[c] + off[c]] = t * 8 + u;
        off[c]++;
    }
}

// ---------------------------------------------------------------------------
// Kernel 2: class-blocked pairwise L1 distance.
// D[i][p] = sum_c |x_i,c - x_j(p),c + EPS|, j(p) = p-th member of class(i).
// Grid: (tiles_j=8, tiles_i=8, class=8), 64x64 tiles, 256 threads, 4x4/thread.
// ---------------------------------------------------------------------------
#define TB 64
#define KC 32

__global__ __launch_bounds__(256, 2)
void dist_kernel(const float* __restrict__ feat) {
    int cls   = blockIdx.z;
    int cnt   = min(g_cnt[cls], MAXC);
    int start = g_start[cls];
    int ti0 = blockIdx.y * TB;
    int tj0 = blockIdx.x * TB;
    if (ti0 >= cnt || tj0 >= cnt) return;

    __shared__ float As[KC][TB];
    __shared__ float Bs[KC][TB];

    int t  = threadIdx.x;
    int tx = t & 15;        // col group
    int ty = t >> 4;        // row group

    float acc[4][4];
#pragma unroll
    for (int a = 0; a < 4; a++)
#pragma unroll
        for (int b = 0; b < 4; b++) acc[a][b] = 0.f;

    // staging: thread t loads row lr (0..63), 8 channels starting at lc
    int lr = t >> 2;
    int lc = (t & 3) * 8;
    int gi = ti0 + lr, gj = tj0 + lr;
    bool av = gi < cnt, bv = gj < cnt;
    const float* arow = feat + (size_t)(av ? g_order[start + gi] : 0) * C;
    const float* brow = feat + (size_t)(bv ? g_order[start + gj] : 0) * C;

    for (int c0 = 0; c0 < C; c0 += KC) {
#pragma unroll
        for (int u = 0; u < 8; u++) {
            float va = av ? arow[c0 + lc + u] : 0.f;
            float vb = bv ? brow[c0 + lc + u] : 0.f;
            As[lc + u][lr] = va + EPS;   // fold eps into the i-side once
            Bs[lc + u][lr] = vb;
        }
        __syncthreads();
#pragma unroll
        for (int kk = 0; kk < KC; kk++) {
            float4 a4 = *(const float4*)&As[kk][ty * 4];
            float4 b4 = *(const float4*)&Bs[kk][tx * 4];
            float av4[4] = {a4.x, a4.y, a4.z, a4.w};
            float bv4[4] = {b4.x, b4.y, b4.z, b4.w};
#pragma unroll
            for (int ii = 0; ii < 4; ii++)
#pragma unroll
                for (int jj = 0; jj < 4; jj++)
                    acc[ii][jj] += fabsf(av4[ii] - bv4[jj]);
        }
        __syncthreads();
    }

#pragma unroll
    for (int ii = 0; ii < 4; ii++) {
        int ti = ti0 + ty * 4 + ii;
        if (ti >= cnt) continue;
        float* dr = g_D + (size_t)g_order[start + ti] * MAXC;
#pragma unroll
        for (int jj = 0; jj < 4; jj++) {
            int tj = tj0 + tx * 4 + jj;
            if (tj < cnt) dr[tj] = (ti == tj) ? finf() : acc[ii][jj];
        }
    }
}

// ---------------------------------------------------------------------------
// Kernel 3: fused top-K selection + neighbor MSE term. One warp per row.
// Grid 256 blocks x 256 threads (8 warps/block).
// ---------------------------------------------------------------------------
__global__ __launch_bounds__(256, 2)
void topk_loss_kernel(const float* __restrict__ feat,
                      const int* __restrict__ target) {
    int warp = threadIdx.x >> 5;
    int lane = threadIdx.x & 31;
    int i = blockIdx.x * 8 + warp;

    int cls   = target[i];
    int cnt   = min(g_cnt[cls], MAXC);
    int start = g_start[cls];
    int m = min(cnt - 1, KSEL);

    float rowloss = 0.f;
    if (m > 0) {
        const float* drow = g_D + (size_t)i * MAXC;
        int nv = (cnt + 31) >> 5;     // occupied 32-wide slots (<= 16)

        float v[16];
#pragma unroll
        for (int s = 0; s < 16; s++) {
            int p = s * 32 + lane;
            v[s] = (s < nv && p < cnt) ? drow[p] : finf();
        }

        int sel[KSEL];
#pragma unroll
        for (int k = 0; k < KSEL; k++) {
            if (k >= m) break;
            float best = finf();
            int   bp   = 0x7fffffff;
#pragma unroll
            for (int s = 0; s < 16; s++) {
                if (s < nv) {
                    int p = s * 32 + lane;
                    if (v[s] < best) { best = v[s]; bp = p; }
                }
            }
            // warp argmin, ties -> lowest index (matches stable top_k)
#pragma unroll
            for (int o = 16; o > 0; o >>= 1) {
                float ov = __shfl_down_sync(0xffffffffu, best, o);
                int   op = __shfl_down_sync(0xffffffffu, bp, o);
                if (ov < best || (ov == best && op < bp)) { best = ov; bp = op; }
            }
            bp = __shfl_sync(0xffffffffu, bp, 0);
            sel[k] = bp;
            // remove winner
#pragma unroll
            for (int s = 0; s < 16; s++) {
                if ((bp >> 5) == s && (bp & 31) == lane) v[s] = finf();
            }
        }

        // loss: sum_{k<m} sum_c (x_i,c - x_j,c / m)^2, lane owns 8 channels
        float inv_m = 1.0f / (float)m;
        const float* xi = feat + (size_t)i * C + lane * 8;
        float4 x0 = *(const float4*)(xi);
        float4 x1 = *(const float4*)(xi + 4);
        float acc = 0.f;
#pragma unroll
        for (int k = 0; k < KSEL; k++) {
            if (k >= m) break;
            int j = g_order[start + sel[k]];
            const float* xj = feat + (size_t)j * C + lane * 8;
            float4 a0 = *(const float4*)(xj);
            float4 a1 = *(const float4*)(xj + 4);
            float d;
            d = x0.x - a0.x * inv_m; acc += d * d;
            d = x0.y - a0.y * inv_m; acc += d * d;
            d = x0.z - a0.z * inv_m; acc += d * d;
            d = x0.w - a0.w * inv_m; acc += d * d;
            d = x1.x - a1.x * inv_m; acc += d * d;
            d = x1.y - a1.y * inv_m; acc += d * d;
            d = x1.z - a1.z * inv_m; acc += d * d;
            d = x1.w - a1.w * inv_m; acc += d * d;
        }
#pragma unroll
        for (int o = 16; o > 0; o >>= 1)
            acc += __shfl_down_sync(0xffffffffu, acc, o);
        rowloss = acc;
    }
    if (lane == 0) g_rowloss[i] = rowloss;
}

// ---------------------------------------------------------------------------
// Kernel 4: CE + final deterministic reduction. One block, 256 threads.
// ---------------------------------------------------------------------------
__global__ __launch_bounds__(256, 1)
void finalize_kernel(const float* __restrict__ scores,
                     const int* __restrict__ target,
                     float* __restrict__ out) {
    __shared__ float sce[256];
    __shared__ float sls[256];
    int t = threadIdx.x;

    float ce = 0.f, ls = 0.f;
    for (int r = t; r < N; r += 256) {
        const float* s = scores + (size_t)r * NCLS;
        float sv[NCLS];
        float mx = -finf();
#pragma unroll
        for (int c = 0; c < NCLS; c++) { sv[c] = s[c]; mx = fmaxf(mx, sv[c]); }
        float se = 0.f;
#pragma unroll
        for (int c = 0; c < NCLS; c++) se += __expf(sv[c] - mx);
        ce += (mx + logf(se)) - sv[target[r]];
        ls += g_rowloss[r];
    }
    sce[t] = ce;
    sls[t] = ls;
    __syncthreads();
    for (int o = 128; o > 0; o >>= 1) {
        if (t < o) { sce[t] += sce[t + o]; sls[t] += sls[t + o]; }
        __syncthreads();
    }
    if (t == 0) out[0] = sce[0] / (float)N + 25.0f * sls[0];  // LAM*0.5 = 25
}

// ---------------------------------------------------------------------------
extern "C" void kernel_launch(void* const* d_in, const int* in_sizes, int n_in,
                              void* d_out, int out_size) {
    const float* feature = (const float*)d_in[0];   // [2048, 256]
    const float* scores  = (const float*)d_in[1];   // [2048, 8]
    const int*   target  = (const int*)d_in[2];     // [2048]
    float* out = (float*)d_out;

    perm_kernel<<<1, 256>>>(target);
    dist_kernel<<<dim3(MAXC / TB, MAXC / TB, NCLS), 256>>>(feature);
    topk_loss_kernel<<<N / 8, 256>>>(feature, target);
    finalize_kernel<<<1, 256>>>(scores, target, out);
}

// round 2
// speedup vs baseline: 1.4292x; 1.4292x over previous
#include <cuda_runtime.h>
#include <cuda_bf16.h>
#include <math.h>

// Problem shape (fixed by setup_inputs)
#define N     2048
#define C     256
#define NCLS  8
#define KSEL  20
#define MAXC  384      // class size bound (binomial mean 256, sd ~15; 384 = +8.5 sd)
#define EPS   1e-6f

typedef unsigned long long u64;

// Scratch (static __device__ — no allocations)
// g_D layout: [2 channel-halves][N rows (original index)][MAXC positions]
__device__ float g_D[2ull * N * MAXC];
__device__ int   g_order[N];
__device__ int   g_start[NCLS];
__device__ int   g_cnt[NCLS];
__device__ float g_partial[256];
__device__ unsigned int g_counter;

__device__ __forceinline__ float finf() { return __int_as_float(0x7f800000); }

__device__ __forceinline__ u64 addx2(u64 a, u64 b) {
    u64 r;
    asm("add.rn.f32x2 %0, %1, %2;" : "=l"(r) : "l"(a), "l"(b));
    return r;
}

// ---------------------------------------------------------------------------
// Kernel 1: stable class-grouping permutation (scan-based, deterministic).
// Also resets the last-block counter for this replay.
// ---------------------------------------------------------------------------
__global__ __launch_bounds__(256, 1)
void perm_kernel(const int* __restrict__ target) {
    __shared__ int sc[256][NCLS];
    int t = threadIdx.x;
    if (t == 0) g_counter = 0u;

    int tg[8];
    int loc[NCLS];
#pragma unroll
    for (int c = 0; c < NCLS; c++) loc[c] = 0;
#pragma unroll
    for (int u = 0; u < 8; u++) {
        tg[u] = target[t * 8 + u];
        loc[tg[u]]++;
    }
#pragma unroll
    for (int c = 0; c < NCLS; c++) sc[t][c] = loc[c];
    __syncthreads();

    for (int ofs = 1; ofs < 256; ofs <<= 1) {
        int add[NCLS];
        if (t >= ofs) {
#pragma unroll
            for (int c = 0; c < NCLS; c++) add[c] = sc[t - ofs][c];
        }
        __syncthreads();
        if (t >= ofs) {
#pragma unroll
            for (int c = 0; c < NCLS; c++) sc[t][c] += add[c];
        }
        __syncthreads();
    }

    __shared__ int start_s[NCLS];
    if (t == 0) {
        int acc = 0;
#pragma unroll
        for (int c = 0; c < NCLS; c++) {
            start_s[c] = acc;
            g_start[c] = acc;
            g_cnt[c]   = sc[255][c];
            acc += sc[255][c];
        }
    }
    __syncthreads();

    int off[NCLS];
#pragma unroll
    for (int c = 0; c < NCLS; c++) off[c] = sc[t][c] - loc[c];
#pragma unroll
    for (int u = 0; u < 8; u++) {
        int c = tg[u];
        g_order[start_s[c] + off[c]] = t * 8 + u;
        off[c]++;
    }
}

// ---------------------------------------------------------------------------
// Kernel 2: class-blocked pairwise L1 distance, packed f32x2, channel-split.
// Each block: one 64x64 tile of one class, one 128-channel half.
// Grid: 576 = 2 halves x 288 tiles, working tiles (5x5 region) enumerated first.
// ---------------------------------------------------------------------------
#define TB 64
#define KC 32   // channels per smem chunk (16 packed pairs)

__global__ __launch_bounds__(256, 2)
void dist_kernel(const float* __restrict__ feat) {
    int bid = blockIdx.x;
    int cs  = (bid >= 288) ? 1 : 0;    // channel half
    int b   = bid - cs * 288;
    int cls, x, y;
    if (b < 200) {                      // 5x5 working region first
        cls = b / 25; int r = b % 25; x = r % 5; y = r / 5;
    } else {                            // 6x6 fringe (x==5 or y==5)
        int e = b - 200; cls = e / 11; int r = e % 11;
        if (r < 6) { x = 5; y = r; } else { x = r - 6; y = 5; }
    }

    int cnt   = min(g_cnt[cls], MAXC);
    int start = g_start[cls];
    int ti0 = y * TB;
    int tj0 = x * TB;
    if (ti0 >= cnt || tj0 >= cnt) return;

    __shared__ float As2[KC / 2][TB][2];   // (a + eps), channel-pair packed
    __shared__ float Bs2[KC / 2][TB][2];   // (-b), channel-pair packed

    int t  = threadIdx.x;
    int tx = t & 15;
    int ty = t >> 4;

    u64 acc2[16];
#pragma unroll
    for (int q = 0; q < 16; q++) acc2[q] = 0ull;

    // staging: thread t loads row lr, 8 channels starting at lc
    int lr = t >> 2;
    int lc = (t & 3) * 8;
    int gi = ti0 + lr, gj = tj0 + lr;
    bool av = gi < cnt, bv = gj < cnt;
    const float* arow = feat + (size_t)(av ? g_order[start + gi] : 0) * C;
    const float* brow = feat + (size_t)(bv ? g_order[start + gj] : 0) * C;

    int cbase = cs * 128;
    for (int c0 = cbase; c0 < cbase + 128; c0 += KC) {
        float4 va0 = make_float4(0.f, 0.f, 0.f, 0.f), va1 = va0;
        float4 vb0 = va0, vb1 = va0;
        if (av) {
            va0 = *(const float4*)(arow + c0 + lc);
            va1 = *(const float4*)(arow + c0 + lc + 4);
        }
        if (bv) {
            vb0 = *(const float4*)(brow + c0 + lc);
            vb1 = *(const float4*)(brow + c0 + lc + 4);
        }
        int p = lc >> 1;
        *(float2*)&As2[p + 0][lr][0] = make_float2(va0.x + EPS, va0.y + EPS);
        *(float2*)&As2[p + 1][lr][0] = make_float2(va0.z + EPS, va0.w + EPS);
        *(float2*)&As2[p + 2][lr][0] = make_float2(va1.x + EPS, va1.y + EPS);
        *(float2*)&As2[p + 3][lr][0] = make_float2(va1.z + EPS, va1.w + EPS);
        *(float2*)&Bs2[p + 0][lr][0] = make_float2(-vb0.x, -vb0.y);
        *(float2*)&Bs2[p + 1][lr][0] = make_float2(-vb0.z, -vb0.w);
        *(float2*)&Bs2[p + 2][lr][0] = make_float2(-vb1.x, -vb1.y);
        *(float2*)&Bs2[p + 3][lr][0] = make_float2(-vb1.z, -vb1.w);
        __syncthreads();

#pragma unroll
        for (int kk2 = 0; kk2 < KC / 2; kk2++) {
            ulonglong2 aL = *(const ulonglong2*)&As2[kk2][ty * 4][0];
            ulonglong2 aH = *(const ulonglong2*)&As2[kk2][ty * 4 + 2][0];
            ulonglong2 bL = *(const ulonglong2*)&Bs2[kk2][tx * 4][0];
            ulonglong2 bH = *(const ulonglong2*)&Bs2[kk2][tx * 4 + 2][0];
            u64 a2[4] = {aL.x, aL.y, aH.x, aH.y};
            u64 b2[4] = {bL.x, bL.y, bH.x, bH.y};
#pragma unroll
            for (int ii = 0; ii < 4; ii++)
#pragma unroll
                for (int jj = 0; jj < 4; jj++) {
                    u64 d = addx2(a2[ii], b2[jj]);          // a + eps - b
                    d &= 0x7FFFFFFF7FFFFFFFull;             // packed |.|
                    acc2[ii * 4 + jj] = addx2(acc2[ii * 4 + jj], d);
                }
        }
        __syncthreads();
    }

    float* dhalf = g_D + (size_t)cs * N * MAXC;
#pragma unroll
    for (int ii = 0; ii < 4; ii++) {
        int ti = ti0 + ty * 4 + ii;
        if (ti >= cnt) continue;
        float* dr = dhalf + (size_t)g_order[start + ti] * MAXC;
#pragma unroll
        for (int jj = 0; jj < 4; jj++) {
            int tj = tj0 + tx * 4 + jj;
            if (tj < cnt) {
                u64 a = acc2[ii * 4 + jj];
                float lo = __uint_as_float((unsigned)(a & 0xFFFFFFFFull));
                float hi = __uint_as_float((unsigned)(a >> 32));
                dr[tj] = (ti == tj) ? finf() : (lo + hi);
            }
        }
    }
}

// ---------------------------------------------------------------------------
// Kernel 3: fused top-K + neighbor MSE + CE + final reduction (last block).
// One warp per row, 256 blocks x 256 threads.
// ---------------------------------------------------------------------------
__global__ __launch_bounds__(256, 2)
void topk_loss_kernel(const float* __restrict__ feat,
                      const float* __restrict__ scores,
                      const int* __restrict__ target,
                      float* __restrict__ out) {
    __shared__ float s_part[8];
    __shared__ bool  s_last;

    int warp = threadIdx.x >> 5;
    int lane = threadIdx.x & 31;
    int i = blockIdx.x * 8 + warp;

    int cls   = target[i];
    int cnt   = min(g_cnt[cls], MAXC);
    int start = g_start[cls];
    int m = min(cnt - 1, KSEL);

    float rowloss = 0.f;
    if (m > 0) {
        const float* d0 = g_D + (size_t)i * MAXC;
        const float* d1 = g_D + (size_t)(N + i) * MAXC;
        int nv = (cnt + 31) >> 5;     // occupied 32-wide slots (<= 12)

        float v[12];
#pragma unroll
        for (int s = 0; s < 12; s++) {
            int p = s * 32 + lane;
            v[s] = (s < nv && p < cnt) ? (d0[p] + d1[p]) : finf();
        }

        int sel[KSEL];
#pragma unroll
        for (int k = 0; k < KSEL; k++) {
            if (k >= m) break;
            float best = finf();
            int   bp   = 0x7fffffff;
#pragma unroll
            for (int s = 0; s < 12; s++) {
                if (s < nv) {
                    int p = s * 32 + lane;
                    if (v[s] < best) { best = v[s]; bp = p; }
                }
            }
#pragma unroll
            for (int o = 16; o > 0; o >>= 1) {
                float ov = __shfl_down_sync(0xffffffffu, best, o);
                int   op = __shfl_down_sync(0xffffffffu, bp, o);
                if (ov < best || (ov == best && op < bp)) { best = ov; bp = op; }
            }
            bp = __shfl_sync(0xffffffffu, bp, 0);
            sel[k] = bp;
#pragma unroll
            for (int s = 0; s < 12; s++) {
                if ((bp >> 5) == s && (bp & 31) == lane) v[s] = finf();
            }
        }

        float inv_m = 1.0f / (float)m;
        const float* xi = feat + (size_t)i * C + lane * 8;
        float4 x0 = *(const float4*)(xi);
        float4 x1 = *(const float4*)(xi + 4);
        float acc = 0.f;
#pragma unroll
        for (int k = 0; k < KSEL; k++) {
            if (k >= m) break;
            int j = g_order[start + sel[k]];
            const float* xj = feat + (size_t)j * C + lane * 8;
            float4 a0 = *(const float4*)(xj);
            float4 a1 = *(const float4*)(xj + 4);
            float d;
            d = x0.x - a0.x * inv_m; acc += d * d;
            d = x0.y - a0.y * inv_m; acc += d * d;
            d = x0.z - a0.z * inv_m; acc += d * d;
            d = x0.w - a0.w * inv_m; acc += d * d;
            d = x1.x - a1.x * inv_m; acc += d * d;
            d = x1.y - a1.y * inv_m; acc += d * d;
            d = x1.z - a1.z * inv_m; acc += d * d;
            d = x1.w - a1.w * inv_m; acc += d * d;
        }
#pragma unroll
        for (int o = 16; o > 0; o >>= 1)
            acc += __shfl_down_sync(0xffffffffu, acc, o);
        rowloss = acc;
    }

    // per-row CE (lane 0), combine with lam term
    if (lane == 0) {
        float4 s0 = *(const float4*)(scores + (size_t)i * NCLS);
        float4 s1 = *(const float4*)(scores + (size_t)i * NCLS + 4);
        float sv[8] = {s0.x, s0.y, s0.z, s0.w, s1.x, s1.y, s1.z, s1.w};
        float mx = sv[0];
#pragma unroll
        for (int c = 1; c < 8; c++) mx = fmaxf(mx, sv[c]);
        float se = 0.f;
#pragma unroll
        for (int c = 0; c < 8; c++) se += __expf(sv[c] - mx);
        float ce = (mx + __logf(se)) - sv[cls];
        s_part[warp] = ce * (1.0f / (float)N) + 25.0f * rowloss;  // LAM*0.5 = 25
    }
    __syncthreads();

    if (threadIdx.x == 0) {
        float p = 0.f;
#pragma unroll
        for (int w = 0; w < 8; w++) p += s_part[w];
        g_partial[blockIdx.x] = p;
        __threadfence();
        unsigned int done = atomicAdd(&g_counter, 1u);
        s_last = (done == 255u);
    }
    __syncthreads();

    if (s_last) {
        __shared__ float sred[256];
        int t = threadIdx.x;
        sred[t] = g_partial[t];
        __syncthreads();
        for (int o = 128; o > 0; o >>= 1) {
            if (t < o) sred[t] += sred[t + o];
            __syncthreads();
        }
        if (t == 0) out[0] = sred[0];
    }
}

// ---------------------------------------------------------------------------
extern "C" void kernel_launch(void* const* d_in, const int* in_sizes, int n_in,
                              void* d_out, int out_size) {
    const float* feature = (const float*)d_in[0];   // [2048, 256]
    const float* scores  = (const float*)d_in[1];   // [2048, 8]
    const int*   target  = (const int*)d_in[2];     // [2048]
    float* out = (float*)d_out;

    perm_kernel<<<1, 256>>>(target);
    dist_kernel<<<576, 256>>>(feature);
    topk_loss_kernel<<<N / 8, 256>>>(feature, scores, target, out);
}

// round 4
// speedup vs baseline: 1.4988x; 1.0487x over previous
#include <cuda_runtime.h>
#include <cuda_bf16.h>
#include <math.h>

// Problem shape (fixed by setup_inputs)
#define N     2048
#define C     256
#define NCLS  8
#define KSEL  20
#define MAXC  384      // class size bound (binomial mean 256, sd ~15)
#define EPS   1e-6f

typedef unsigned long long u64;

// Scratch (static __device__ — no allocations)
// g_D layout: [2 channel-halves][N rows (original index)][MAXC positions]
__device__ float g_D[2ull * N * MAXC];
__device__ int   g_orderC[NCLS * MAXC];   // per-class member lists (original indices)
__device__ int   g_cntC[NCLS];
__device__ float g_partial[256];
__device__ unsigned int g_counter;

__device__ __forceinline__ float finf() { return __int_as_float(0x7f800000); }

__device__ __forceinline__ u64 addx2(u64 a, u64 b) {
    u64 r;
    asm("add.rn.f32x2 %0, %1, %2;" : "=l"(r) : "l"(a), "l"(b));
    return r;
}

// ---------------------------------------------------------------------------
// Kernel 1: class-blocked pairwise L1 distance, packed f32x2, channel-split.
// Each block rebuilds its class member list locally (no separate perm kernel).
// Blocks at (x=0,y=0,cs=0) publish the list for the topk kernel.
// Grid: 576 = 2 halves x (8 classes x 36 tiles), 5x5 working region first.
// ---------------------------------------------------------------------------
#define TB 64
#define KC 64   // channels per smem chunk (32 packed pairs)

__global__ __launch_bounds__(256, 2)
void dist_kernel(const float* __restrict__ feat, const int* __restrict__ target) {
    int bid = blockIdx.x;
    if (bid == 0 && threadIdx.x == 0) g_counter = 0u;   // reset for topk

    int cs  = (bid >= 288) ? 1 : 0;    // channel half
    int b   = bid - cs * 288;
    int cls, x, y;
    if (b < 200) {                      // 5x5 working region first
        cls = b / 25; int r = b % 25; x = r % 5; y = r / 5;
    } else {                            // 6x6 fringe (x==5 or y==5)
        int e = b - 200; cls = e / 11; int r = e % 11;
        if (r < 6) { x = 5; y = r; } else { x = r - 6; y = 5; }
    }

    // ---- smem (tile arrays MUST be 16B-aligned: ulonglong2 loads) ----
    __shared__ __align__(16) float As2[KC / 2][TB][2];   // (a + eps), pair packed
    __shared__ __align__(16) float Bs2[KC / 2][TB][2];   // (-b), pair packed
    __shared__ __align__(16) int   list[MAXC];
    __shared__ int   s_wofs[8];
    __shared__ int   s_cnt;

    // ---- build member list for this class in smem (stable, deterministic) ----
    int t    = threadIdx.x;
    int lane = t & 31;
    int w    = t >> 5;

    int4 t0 = *(const int4*)(target + t * 8);
    int4 t1 = *(const int4*)(target + t * 8 + 4);
    int tg[8] = {t0.x, t0.y, t0.z, t0.w, t1.x, t1.y, t1.z, t1.w};
    int mcount = 0;
#pragma unroll
    for (int u = 0; u < 8; u++) mcount += (tg[u] == cls);

    int incl = mcount;
#pragma unroll
    for (int o = 1; o < 32; o <<= 1) {
        int v = __shfl_up_sync(0xffffffffu, incl, o);
        if (lane >= o) incl += v;
    }
    if (lane == 31) s_wofs[w] = incl;
    __syncthreads();
    if (t == 0) {
        int acc = 0;
#pragma unroll
        for (int ww = 0; ww < 8; ww++) { int v = s_wofs[ww]; s_wofs[ww] = acc; acc += v; }
        s_cnt = acc;
    }
    __syncthreads();
    int base = s_wofs[w] + incl - mcount;   // exclusive prefix for this thread
#pragma unroll
    for (int u = 0; u < 8; u++) {
        if (tg[u] == cls && base < MAXC) { list[base] = t * 8 + u; base++; }
    }
    __syncthreads();
    int cnt = min(s_cnt, MAXC);

    // publisher blocks export the list for topk (one block per class, cs==0)
    if (cs == 0 && x == 0 && y == 0) {
        if (t == 0) g_cntC[cls] = cnt;
        for (int p = t; p < cnt; p += 256) g_orderC[cls * MAXC + p] = list[p];
    }

    int ti0 = y * TB;
    int tj0 = x * TB;
    if (ti0 >= cnt || tj0 >= cnt) return;

    int tx = t & 15;
    int ty = t >> 4;

    u64 acc2[16];
#pragma unroll
    for (int q = 0; q < 16; q++) acc2[q] = 0ull;

    // staging: thread t loads row lr, 16 channels starting at lc
    int lr = t >> 2;
    int lc = (t & 3) * 16;
    int gi = ti0 + lr, gj = tj0 + lr;
    bool av = gi < cnt, bv = gj < cnt;
    const float* arow = feat + (size_t)(av ? list[gi] : 0) * C;
    const float* brow = feat + (size_t)(bv ? list[gj] : 0) * C;

    int cbase = cs * 128;
    for (int c0 = cbase; c0 < cbase + 128; c0 += KC) {
#pragma unroll
        for (int h = 0; h < 2; h++) {
            float4 va0 = make_float4(0.f, 0.f, 0.f, 0.f), va1 = va0;
            float4 vb0 = va0, vb1 = va0;
            int cc = c0 + lc + h * 8;
            if (av) {
                va0 = *(const float4*)(arow + cc);
                va1 = *(const float4*)(arow + cc + 4);
            }
            if (bv) {
                vb0 = *(const float4*)(brow + cc);
                vb1 = *(const float4*)(brow + cc + 4);
            }
            int p = (lc + h * 8) >> 1;
            *(float2*)&As2[p + 0][lr][0] = make_float2(va0.x + EPS, va0.y + EPS);
            *(float2*)&As2[p + 1][lr][0] = make_float2(va0.z + EPS, va0.w + EPS);
            *(float2*)&As2[p + 2][lr][0] = make_float2(va1.x + EPS, va1.y + EPS);
            *(float2*)&As2[p + 3][lr][0] = make_float2(va1.z + EPS, va1.w + EPS);
            *(float2*)&Bs2[p + 0][lr][0] = make_float2(-vb0.x, -vb0.y);
            *(float2*)&Bs2[p + 1][lr][0] = make_float2(-vb0.z, -vb0.w);
            *(float2*)&Bs2[p + 2][lr][0] = make_float2(-vb1.x, -vb1.y);
            *(float2*)&Bs2[p + 3][lr][0] = make_float2(-vb1.z, -vb1.w);
        }
        __syncthreads();

#pragma unroll
        for (int kk2 = 0; kk2 < KC / 2; kk2++) {
            ulonglong2 aL = *(const ulonglong2*)&As2[kk2][ty * 4][0];
            ulonglong2 aH = *(const ulonglong2*)&As2[kk2][ty * 4 + 2][0];
            ulonglong2 bL = *(const ulonglong2*)&Bs2[kk2][tx * 4][0];
            ulonglong2 bH = *(const ulonglong2*)&Bs2[kk2][tx * 4 + 2][0];
            u64 a2[4] = {aL.x, aL.y, aH.x, aH.y};
            u64 b2[4] = {bL.x, bL.y, bH.x, bH.y};
#pragma unroll
            for (int ii = 0; ii < 4; ii++)
#pragma unroll
                for (int jj = 0; jj < 4; jj++) {
                    u64 d = addx2(a2[ii], b2[jj]);          // a + eps - b
                    d &= 0x7FFFFFFF7FFFFFFFull;             // packed |.|
                    acc2[ii * 4 + jj] = addx2(acc2[ii * 4 + jj], d);
                }
        }
        __syncthreads();
    }

    float* dhalf = g_D + (size_t)cs * N * MAXC;
#pragma unroll
    for (int ii = 0; ii < 4; ii++) {
        int ti = ti0 + ty * 4 + ii;
        if (ti >= cnt) continue;
        float* dr = dhalf + (size_t)list[ti] * MAXC;
#pragma unroll
        for (int jj = 0; jj < 4; jj++) {
            int tj = tj0 + tx * 4 + jj;
            if (tj < cnt) {
                u64 a = acc2[ii * 4 + jj];
                float lo = __uint_as_float((unsigned)(a & 0xFFFFFFFFull));
                float hi = __uint_as_float((unsigned)(a >> 32));
                dr[tj] = (ti == tj) ? finf() : (lo + hi);
            }
        }
    }
}

// ---------------------------------------------------------------------------
// Kernel 2: fused top-K + neighbor MSE + CE + final reduction (last block).
// One warp per row, 256 blocks x 256 threads.
// ---------------------------------------------------------------------------
__global__ __launch_bounds__(256, 2)
void topk_loss_kernel(const float* __restrict__ feat,
                      const float* __restrict__ scores,
                      const int* __restrict__ target,
                      float* __restrict__ out) {
    __shared__ float s_part[8];
    __shared__ bool  s_last;

    int warp = threadIdx.x >> 5;
    int lane = threadIdx.x & 31;
    int i = blockIdx.x * 8 + warp;

    int cls = target[i];
    int cnt = min(g_cntC[cls], MAXC);
    const int* order = g_orderC + cls * MAXC;
    int m = min(cnt - 1, KSEL);

    float rowloss = 0.f;
    if (m > 0) {
        const float* d0 = g_D + (size_t)i * MAXC;
        const float* d1 = g_D + (size_t)(N + i) * MAXC;
        int nv = (cnt + 31) >> 5;     // occupied 32-wide slots (<= 12)

        float v[12];
#pragma unroll
        for (int s = 0; s < 12; s++) {
            int p = s * 32 + lane;
            v[s] = (s < nv && p < cnt) ? (d0[p] + d1[p]) : finf();
        }

        int sel[KSEL];
#pragma unroll
        for (int k = 0; k < KSEL; k++) {
            if (k >= m) break;
            float best = finf();
            int   bp   = 0x7fffffff;
#pragma unroll
            for (int s = 0; s < 12; s++) {
                if (s < nv) {
                    int p = s * 32 + lane;
                    if (v[s] < best) { best = v[s]; bp = p; }
                }
            }
#pragma unroll
            for (int o = 16; o > 0; o >>= 1) {
                float ov = __shfl_down_sync(0xffffffffu, best, o);
                int   op = __shfl_down_sync(0xffffffffu, bp, o);
                if (ov < best || (ov == best && op < bp)) { best = ov; bp = op; }
            }
            bp = __shfl_sync(0xffffffffu, bp, 0);
            sel[k] = bp;
#pragma unroll
            for (int s = 0; s < 12; s++) {
                if ((bp >> 5) == s && (bp & 31) == lane) v[s] = finf();
            }
        }

        float inv_m = 1.0f / (float)m;
        const float* xi = feat + (size_t)i * C + lane * 8;
        float4 x0 = *(const float4*)(xi);
        float4 x1 = *(const float4*)(xi + 4);
        float acc = 0.f;
#pragma unroll
        for (int k = 0; k < KSEL; k++) {
            if (k >= m) break;
            int j = order[sel[k]];
            const float* xj = feat + (size_t)j * C + lane * 8;
            float4 a0 = *(const float4*)(xj);
            float4 a1 = *(const float4*)(xj + 4);
            float d;
            d = x0.x - a0.x * inv_m; acc += d * d;
            d = x0.y - a0.y * inv_m; acc += d * d;
            d = x0.z - a0.z * inv_m; acc += d * d;
            d = x0.w - a0.w * inv_m; acc += d * d;
            d = x1.x - a1.x * inv_m; acc += d * d;
            d = x1.y - a1.y * inv_m; acc += d * d;
            d = x1.z - a1.z * inv_m; acc += d * d;
            d = x1.w - a1.w * inv_m; acc += d * d;
        }
#pragma unroll
        for (int o = 16; o > 0; o >>= 1)
            acc += __shfl_down_sync(0xffffffffu, acc, o);
        rowloss = acc;
    }

    // per-row CE (lane 0), combine with lam term
    if (lane == 0) {
        float4 s0 = *(const float4*)(scores + (size_t)i * NCLS);
        float4 s1 = *(const float4*)(scores + (size_t)i * NCLS + 4);
        float sv[8] = {s0.x, s0.y, s0.z, s0.w, s1.x, s1.y, s1.z, s1.w};
        float mx = sv[0];
#pragma unroll
        for (int c = 1; c < 8; c++) mx = fmaxf(mx, sv[c]);
        float se = 0.f;
#pragma unroll
        for (int c = 0; c < 8; c++) se += __expf(sv[c] - mx);
        float ce = (mx + __logf(se)) - sv[cls];
        s_part[warp] = ce * (1.0f / (float)N) + 25.0f * rowloss;  // LAM*0.5 = 25
    }
    __syncthreads();

    if (threadIdx.x == 0) {
        float p = 0.f;
#pragma unroll
        for (int w = 0; w < 8; w++) p += s_part[w];
        g_partial[blockIdx.x] = p;
        __threadfence();
        unsigned int done = atomicAdd(&g_counter, 1u);
        s_last = (done == 255u);
    }
    __syncthreads();

    if (s_last) {
        __shared__ float sred[256];
        int t = threadIdx.x;
        sred[t] = g_partial[t];
        __syncthreads();
        for (int o = 128; o > 0; o >>= 1) {
            if (t < o) sred[t] += sred[t + o];
            __syncthreads();
        }
        if (t == 0) out[0] = sred[0];
    }
}

// ---------------------------------------------------------------------------
extern "C" void kernel_launch(void* const* d_in, const int* in_sizes, int n_in,
                              void* d_out, int out_size) {
    const float* feature = (const float*)d_in[0];   // [2048, 256]
    const float* scores  = (const float*)d_in[1];   // [2048, 8]
    const int*   target  = (const int*)d_in[2];     // [2048]
    float* out = (float*)d_out;

    dist_kernel<<<576, 256>>>(feature, target);
    topk_loss_kernel<<<N / 8, 256>>>(feature, scores, target, out);
}

// round 5
// speedup vs baseline: 1.5299x; 1.0207x over previous
#include <cuda_runtime.h>
#include <cuda_bf16.h>
#include <math.h>

// Problem shape (fixed by setup_inputs)
#define N     2048
#define C     256
#define NCLS  8
#define KSEL  20
#define MAXC  384      // class size bound; tiles cover 6*64=384
#define EPS   1e-6f

typedef unsigned long long u64;

// Scratch (static __device__ — no allocations)
// g_D layout: [2 channel-halves][N rows (original index)][MAXC positions]
__device__ float g_D[2ull * N * MAXC];
__device__ int   g_orderC[NCLS * MAXC];   // per-class member lists (original indices)
__device__ int   g_cntC[NCLS];
__device__ float g_partial[256];
__device__ unsigned int g_counter;

__device__ __forceinline__ float finf() { return __int_as_float(0x7f800000); }

__device__ __forceinline__ u64 addx2(u64 a, u64 b) {
    u64 r;
    asm("add.rn.f32x2 %0, %1, %2;" : "=l"(r) : "l"(a), "l"(b));
    return r;
}

// ---------------------------------------------------------------------------
// Kernel 1: class-blocked pairwise L1 distance, packed f32x2, channel-split.
// 512 threads, 2x4 micro-tile (16 acc regs) -> 32 warps/SM (50% occ).
// Register-prefetch double buffering over 4 K-chunks of 32 channels.
// Grid: 576 = 2 halves x (8 classes x 36 tiles), 5x5 working region first.
// ---------------------------------------------------------------------------
#define TB 64
#define KC 32   // channels per smem chunk (16 packed pairs)

__global__ __launch_bounds__(512, 2)
void dist_kernel(const float* __restrict__ feat, const int* __restrict__ target) {
    int bid = blockIdx.x;
    if (bid == 0 && threadIdx.x == 0) g_counter = 0u;   // reset for topk

    int cs  = (bid >= 288) ? 1 : 0;    // channel half
    int b   = bid - cs * 288;
    int cls, x, y;
    if (b < 200) {                      // 5x5 working region first
        cls = b / 25; int r = b % 25; x = r % 5; y = r / 5;
    } else {                            // 6x6 fringe (x==5 or y==5)
        int e = b - 200; cls = e / 11; int r = e % 11;
        if (r < 6) { x = 5; y = r; } else { x = r - 6; y = 5; }
    }

    // ---- smem (tile arrays MUST be 16B-aligned: ulonglong2 loads) ----
    __shared__ __align__(16) float As2[KC / 2][TB][2];   // (a + eps), pair packed
    __shared__ __align__(16) float Bs2[KC / 2][TB][2];   // (-b), pair packed
    __shared__ __align__(16) int   list[MAXC];
    __shared__ int   s_wofs[16];
    __shared__ int   s_cnt;

    // ---- build member list for this class in smem (stable, deterministic) ----
    int t    = threadIdx.x;
    int lane = t & 31;
    int w    = t >> 5;

    int4 t0 = *(const int4*)(target + t * 4);
    int tg[4] = {t0.x, t0.y, t0.z, t0.w};
    int mcount = 0;
#pragma unroll
    for (int u = 0; u < 4; u++) mcount += (tg[u] == cls);

    int incl = mcount;
#pragma unroll
    for (int o = 1; o < 32; o <<= 1) {
        int v = __shfl_up_sync(0xffffffffu, incl, o);
        if (lane >= o) incl += v;
    }
    if (lane == 31) s_wofs[w] = incl;
    __syncthreads();
    if (t == 0) {
        int acc = 0;
#pragma unroll
        for (int ww = 0; ww < 16; ww++) { int v = s_wofs[ww]; s_wofs[ww] = acc; acc += v; }
        s_cnt = acc;
    }
    __syncthreads();
    int base = s_wofs[w] + incl - mcount;   // exclusive prefix for this thread
#pragma unroll
    for (int u = 0; u < 4; u++) {
        if (tg[u] == cls && base < MAXC) { list[base] = t * 4 + u; base++; }
    }
    __syncthreads();
    int cnt = min(s_cnt, MAXC);
    for (int p = cnt + t; p < MAXC; p += 512) list[p] = 0;   // safe padding
    __syncthreads();

    // publisher blocks export the list for topk (one block per class, cs==0)
    if (cs == 0 && x == 0 && y == 0) {
        if (t == 0) g_cntC[cls] = cnt;
        for (int p = t; p < cnt; p += 512) g_orderC[cls * MAXC + p] = list[p];
    }

    int ti0 = y * TB;
    int tj0 = x * TB;
    if (ti0 >= cnt || tj0 >= cnt) return;

    int tx  = t & 15;     // j-group: 4 cols
    int tiy = t >> 4;     // i-group: 2 rows (0..31)

    u64 acc2[2][4];
#pragma unroll
    for (int r = 0; r < 2; r++)
#pragma unroll
        for (int c = 0; c < 4; c++) acc2[r][c] = 0ull;

    // staging assignment: thread t loads row lr, 4 channels starting at lc
    int lr = t >> 3;            // 0..63
    int lc = (t & 7) * 4;       // 0..28
    int gi = ti0 + lr, gj = tj0 + lr;
    bool av = gi < cnt, bv = gj < cnt;
    const float* arow = feat + (size_t)(av ? list[gi] : 0) * C;
    const float* brow = feat + (size_t)(bv ? list[gj] : 0) * C;

    int cbase = cs * 128;
    float4 pa = make_float4(0.f, 0.f, 0.f, 0.f), pb = pa;
    if (av) pa = *(const float4*)(arow + cbase + lc);
    if (bv) pb = *(const float4*)(brow + cbase + lc);

    for (int ch = 0; ch < 4; ch++) {
        __syncthreads();   // previous inner loop done before overwrite
        int p = lc >> 1;
        *(float2*)&As2[p + 0][lr][0] = make_float2(pa.x + EPS, pa.y + EPS);
        *(float2*)&As2[p + 1][lr][0] = make_float2(pa.z + EPS, pa.w + EPS);
        *(float2*)&Bs2[p + 0][lr][0] = make_float2(-pb.x, -pb.y);
        *(float2*)&Bs2[p + 1][lr][0] = make_float2(-pb.z, -pb.w);
        __syncthreads();

        if (ch < 3) {      // prefetch next chunk while computing
            int cc = cbase + (ch + 1) * KC + lc;
            if (av) pa = *(const float4*)(arow + cc);
            if (bv) pb = *(const float4*)(brow + cc);
        }

#pragma unroll
        for (int kk2 = 0; kk2 < KC / 2; kk2++) {
            ulonglong2 aa = *(const ulonglong2*)&As2[kk2][tiy * 2][0];
            ulonglong2 b0 = *(const ulonglong2*)&Bs2[kk2][tx * 4][0];
            ulonglong2 b1 = *(const ulonglong2*)&Bs2[kk2][tx * 4 + 2][0];
            u64 a2[2] = {aa.x, aa.y};
            u64 b2[4] = {b0.x, b0.y, b1.x, b1.y};
#pragma unroll
            for (int r = 0; r < 2; r++)
#pragma unroll
                for (int c = 0; c < 4; c++) {
                    u64 d = addx2(a2[r], b2[c]);            // a + eps - b
                    d &= 0x7FFFFFFF7FFFFFFFull;             // packed |.|
                    acc2[r][c] = addx2(acc2[r][c], d);
                }
        }
    }

    float* dhalf = g_D + (size_t)cs * N * MAXC;
#pragma unroll
    for (int r = 0; r < 2; r++) {
        int ti = ti0 + tiy * 2 + r;
        if (ti >= cnt) continue;
        float o[4];
#pragma unroll
        for (int c = 0; c < 4; c++) {
            u64 a = acc2[r][c];
            float lo = __uint_as_float((unsigned)(a & 0xFFFFFFFFull));
            float hi = __uint_as_float((unsigned)(a >> 32));
            int tj = tj0 + tx * 4 + c;
            o[c] = (ti == tj) ? finf() : (lo + hi);
        }
        // tj columns always < MAXC; junk beyond cnt never read
        *(float4*)(dhalf + (size_t)list[ti] * MAXC + tj0 + tx * 4) =
            make_float4(o[0], o[1], o[2], o[3]);
    }
}

// ---------------------------------------------------------------------------
// Kernel 2: fused top-K + neighbor MSE + CE + final reduction (last block).
// One warp per row. Packed 32-bit keys (value|index) + argmin-2 rounds:
// 10 rounds pick 2 winners each -> half the shfl-chain latency.
// ---------------------------------------------------------------------------
__global__ __launch_bounds__(256, 2)
void topk_loss_kernel(const float* __restrict__ feat,
                      const float* __restrict__ scores,
                      const int* __restrict__ target,
                      float* __restrict__ out) {
    __shared__ float s_part[8];
    __shared__ bool  s_last;

    int warp = threadIdx.x >> 5;
    int lane = threadIdx.x & 31;
    int i = blockIdx.x * 8 + warp;

    int cls = target[i];
    int cnt = min(g_cntC[cls], MAXC);
    const int* order = g_orderC + cls * MAXC;
    int m = min(cnt - 1, KSEL);

    float rowloss = 0.f;
    if (m > 0) {
        const float* d0 = g_D + (size_t)i * MAXC;
        const float* d1 = g_D + (size_t)(N + i) * MAXC;

        // packed keys: high 23 bits of distance | 9-bit position
        unsigned v[12];
#pragma unroll
        for (int s = 0; s < 12; s++) {
            int p = s * 32 + lane;
            if (p < cnt) {
                float d = d0[p] + d1[p];
                v[s] = (__float_as_uint(d) & 0xFFFFFE00u) | (unsigned)p;
            } else {
                v[s] = 0xFFFFFFFFu;
            }
        }

        unsigned mypos = 0;
#pragma unroll
        for (int r = 0; r < 10; r++) {
            // local two smallest of 12 slots
            unsigned k1 = 0xFFFFFFFFu, k2 = 0xFFFFFFFFu;
#pragma unroll
            for (int s = 0; s < 12; s++) {
                unsigned xv = v[s];
                unsigned nk2 = min(k2, max(k1, xv));
                k1 = min(k1, xv);
                k2 = nk2;
            }
            // warp-wide two smallest
#pragma unroll
            for (int o = 16; o > 0; o >>= 1) {
                unsigned p1 = __shfl_down_sync(0xffffffffu, k1, o);
                unsigned p2 = __shfl_down_sync(0xffffffffu, k2, o);
                unsigned hi = max(k1, p1);
                k1 = min(k1, p1);
                k2 = min(hi, min(k2, p2));
            }
            unsigned w1 = __shfl_sync(0xffffffffu, k1, 0);
            unsigned w2 = __shfl_sync(0xffffffffu, k2, 0);
            if (lane == 2 * r)     mypos = w1 & 511u;
            if (lane == 2 * r + 1) mypos = w2 & 511u;
#pragma unroll
            for (int s = 0; s < 12; s++) {
                if (v[s] == w1 || v[s] == w2) v[s] = 0xFFFFFFFFu;
            }
        }

        // MSE gather: lane owns 8 channels; 20 neighbor indices broadcast.
        float inv_m = 1.0f / (float)m;
        const float* xi = feat + (size_t)i * C + lane * 8;
        float4 x0 = *(const float4*)(xi);
        float4 x1 = *(const float4*)(xi + 4);
        float acc = 0.f;
#pragma unroll
        for (int k = 0; k < KSEL; k++) {
            bool valid = (k < m);
            unsigned p = __shfl_sync(0xffffffffu, mypos, k);
            int j = order[valid ? p : 0];
            const float* xj = feat + (size_t)j * C + lane * 8;
            float4 a0 = *(const float4*)(xj);
            float4 a1 = *(const float4*)(xj + 4);
            float s = 0.f, d;
            d = x0.x - a0.x * inv_m; s += d * d;
            d = x0.y - a0.y * inv_m; s += d * d;
            d = x0.z - a0.z * inv_m; s += d * d;
            d = x0.w - a0.w * inv_m; s += d * d;
            d = x1.x - a1.x * inv_m; s += d * d;
            d = x1.y - a1.y * inv_m; s += d * d;
            d = x1.z - a1.z * inv_m; s += d * d;
            d = x1.w - a1.w * inv_m; s += d * d;
            acc += valid ? s : 0.f;
        }
#pragma unroll
        for (int o = 16; o > 0; o >>= 1)
            acc += __shfl_down_sync(0xffffffffu, acc, o);
        rowloss = acc;
    }

    // per-row CE (lane 0), combine with lam term
    if (lane == 0) {
        float4 s0 = *(const float4*)(scores + (size_t)i * NCLS);
        float4 s1 = *(const float4*)(scores + (size_t)i * NCLS + 4);
        float sv[8] = {s0.x, s0.y, s0.z, s0.w, s1.x, s1.y, s1.z, s1.w};
        float mx = sv[0];
#pragma unroll
        for (int c = 1; c < 8; c++) mx = fmaxf(mx, sv[c]);
        float se = 0.f;
#pragma unroll
        for (int c = 0; c < 8; c++) se += __expf(sv[c] - mx);
        float ce = (mx + __logf(se)) - sv[cls];
        s_part[warp] = ce * (1.0f / (float)N) + 25.0f * rowloss;  // LAM*0.5 = 25
    }
    __syncthreads();

    if (threadIdx.x == 0) {
        float p = 0.f;
#pragma unroll
        for (int w = 0; w < 8; w++) p += s_part[w];
        g_partial[blockIdx.x] = p;
        __threadfence();
        unsigned int done = atomicAdd(&g_counter, 1u);
        s_last = (done == 255u);
    }
    __syncthreads();

    if (s_last) {
        __shared__ float sred[256];
        int t = threadIdx.x;
        sred[t] = g_partial[t];
        __syncthreads();
        for (int o = 128; o > 0; o >>= 1) {
            if (t < o) sred[t] += sred[t + o];
            __syncthreads();
        }
        if (t == 0) out[0] = sred[0];
    }
}

// ---------------------------------------------------------------------------
extern "C" void kernel_launch(void* const* d_in, const int* in_sizes, int n_in,
                              void* d_out, int out_size) {
    const float* feature = (const float*)d_in[0];   // [2048, 256]
    const float* scores  = (const float*)d_in[1];   // [2048, 8]
    const int*   target  = (const int*)d_in[2];     // [2048]
    float* out = (float*)d_out;

    dist_kernel<<<576, 512>>>(feature, target);
    topk_loss_kernel<<<N / 8, 256>>>(feature, scores, target, out);
}

// round 6
// speedup vs baseline: 1.9938x; 1.3032x over previous
#include <cuda_runtime.h>
#include <cuda_bf16.h>
#include <math.h>

// Problem shape (fixed by setup_inputs)
#define N     2048
#define C     256
#define NCLS  8
#define KSEL  20
#define MAXC  384      // class size bound; tiles cover 6*64=384
#define EPS   1e-6f

typedef unsigned long long u64;

// Scratch (static __device__ — no allocations)
// g_D layout: [2 channel-halves][N rows (original index)][MAXC positions]
__device__ float g_D[2ull * N * MAXC];
__device__ int   g_orderC[NCLS * MAXC];   // per-class member lists (original indices)
__device__ int   g_cntC[NCLS];
__device__ float g_partial[256];
__device__ unsigned int g_counter;

__device__ __forceinline__ float finf() { return __int_as_float(0x7f800000); }

__device__ __forceinline__ u64 addx2(u64 a, u64 b) {
    u64 r;
    asm("add.rn.f32x2 %0, %1, %2;" : "=l"(r) : "l"(a), "l"(b));
    return r;
}

// ---------------------------------------------------------------------------
// Kernel 1: class-blocked pairwise L1 distance, packed f32x2, channel-split.
// 256 threads, 4x4 micro-tile, KC=32, DOUBLE-BUFFERED smem (1 sync/chunk),
// register prefetch of next chunk, 3 blocks/SM (24 warps).
// Grid: 576 = 2 halves x (8 classes x 36 tiles), 5x5 working region first.
// ---------------------------------------------------------------------------
#define TB 64
#define KC 32   // channels per smem chunk (16 packed pairs)

__global__ __launch_bounds__(256, 3)
void dist_kernel(const float* __restrict__ feat, const int* __restrict__ target) {
    int bid = blockIdx.x;
    if (bid == 0 && threadIdx.x == 0) g_counter = 0u;   // reset for topk

    int cs  = (bid >= 288) ? 1 : 0;    // channel half
    int b   = bid - cs * 288;
    int cls, x, y;
    if (b < 200) {                      // 5x5 working region first
        cls = b / 25; int r = b % 25; x = r % 5; y = r / 5;
    } else {                            // 6x6 fringe (x==5 or y==5)
        int e = b - 200; cls = e / 11; int r = e % 11;
        if (r < 6) { x = 5; y = r; } else { x = r - 6; y = 5; }
    }

    // ---- smem (tile arrays MUST be 16B-aligned: ulonglong2 loads) ----
    __shared__ __align__(16) float As2[2][KC / 2][TB][2];   // (a + eps), pair packed
    __shared__ __align__(16) float Bs2[2][KC / 2][TB][2];   // (-b), pair packed
    __shared__ __align__(16) int   list[MAXC];
    __shared__ int   s_wofs[8];
    __shared__ int   s_cnt;

    // ---- build member list for this class in smem (stable, deterministic) ----
    int t    = threadIdx.x;
    int lane = t & 31;
    int w    = t >> 5;

    int4 t0 = *(const int4*)(target + t * 8);
    int4 t1 = *(const int4*)(target + t * 8 + 4);
    int tg[8] = {t0.x, t0.y, t0.z, t0.w, t1.x, t1.y, t1.z, t1.w};
    int mcount = 0;
#pragma unroll
    for (int u = 0; u < 8; u++) mcount += (tg[u] == cls);

    int incl = mcount;
#pragma unroll
    for (int o = 1; o < 32; o <<= 1) {
        int v = __shfl_up_sync(0xffffffffu, incl, o);
        if (lane >= o) incl += v;
    }
    if (lane == 31) s_wofs[w] = incl;
    __syncthreads();
    if (t == 0) {
        int acc = 0;
#pragma unroll
        for (int ww = 0; ww < 8; ww++) { int v = s_wofs[ww]; s_wofs[ww] = acc; acc += v; }
        s_cnt = acc;
    }
    __syncthreads();
    int base = s_wofs[w] + incl - mcount;   // exclusive prefix for this thread
#pragma unroll
    for (int u = 0; u < 8; u++) {
        if (tg[u] == cls && base < MAXC) { list[base] = t * 8 + u; base++; }
    }
    __syncthreads();
    int cnt = min(s_cnt, MAXC);
    for (int p = cnt + t; p < MAXC; p += 256) list[p] = 0;   // safe padding
    __syncthreads();

    // publisher blocks export the list for topk (one block per class, cs==0)
    if (cs == 0 && x == 0 && y == 0) {
        if (t == 0) g_cntC[cls] = cnt;
        for (int p = t; p < cnt; p += 256) g_orderC[cls * MAXC + p] = list[p];
    }

    int ti0 = y * TB;
    int tj0 = x * TB;
    if (ti0 >= cnt || tj0 >= cnt) return;

    int tx = t & 15;      // j-group: 4 cols
    int ty = t >> 4;      // i-group: 4 rows

    u64 acc2[16];
#pragma unroll
    for (int q = 0; q < 16; q++) acc2[q] = 0ull;

    // staging assignment: thread t loads row lr, 8 channels starting at lc
    int lr = t >> 2;            // 0..63
    int lc = (t & 3) * 8;       // 0..24
    int gi = ti0 + lr, gj = tj0 + lr;
    bool av = gi < cnt, bv = gj < cnt;
    const float* arow = feat + (size_t)(av ? list[gi] : 0) * C;
    const float* brow = feat + (size_t)(bv ? list[gj] : 0) * C;

    int cbase = cs * 128;
    float4 z4 = make_float4(0.f, 0.f, 0.f, 0.f);
    float4 pa0 = z4, pa1 = z4, pb0 = z4, pb1 = z4;

#define LOADCHUNK(CH) do {                                        \
        int cc = cbase + (CH) * KC + lc;                          \
        if (av) { pa0 = *(const float4*)(arow + cc);              \
                  pa1 = *(const float4*)(arow + cc + 4); }        \
        if (bv) { pb0 = *(const float4*)(brow + cc);              \
                  pb1 = *(const float4*)(brow + cc + 4); }        \
    } while (0)

#define STORECHUNK(B) do {                                                     \
        int p = lc >> 1;                                                       \
        *(float2*)&As2[B][p + 0][lr][0] = make_float2(pa0.x + EPS, pa0.y + EPS); \
        *(float2*)&As2[B][p + 1][lr][0] = make_float2(pa0.z + EPS, pa0.w + EPS); \
        *(float2*)&As2[B][p + 2][lr][0] = make_float2(pa1.x + EPS, pa1.y + EPS); \
        *(float2*)&As2[B][p + 3][lr][0] = make_float2(pa1.z + EPS, pa1.w + EPS); \
        *(float2*)&Bs2[B][p + 0][lr][0] = make_float2(-pb0.x, -pb0.y);           \
        *(float2*)&Bs2[B][p + 1][lr][0] = make_float2(-pb0.z, -pb0.w);           \
        *(float2*)&Bs2[B][p + 2][lr][0] = make_float2(-pb1.x, -pb1.y);           \
        *(float2*)&Bs2[B][p + 3][lr][0] = make_float2(-pb1.z, -pb1.w);           \
    } while (0)

    LOADCHUNK(0);
    STORECHUNK(0);
    __syncthreads();

#pragma unroll
    for (int ch = 0; ch < 4; ch++) {
        if (ch < 3) LOADCHUNK(ch + 1);      // LDG hides under compute below
        int buf = ch & 1;
#pragma unroll
        for (int kk2 = 0; kk2 < KC / 2; kk2++) {
            ulonglong2 aL = *(const ulonglong2*)&As2[buf][kk2][ty * 4][0];
            ulonglong2 aH = *(const ulonglong2*)&As2[buf][kk2][ty * 4 + 2][0];
            ulonglong2 bL = *(const ulonglong2*)&Bs2[buf][kk2][tx * 4][0];
            ulonglong2 bH = *(const ulonglong2*)&Bs2[buf][kk2][tx * 4 + 2][0];
            u64 a2[4] = {aL.x, aL.y, aH.x, aH.y};
            u64 b2[4] = {bL.x, bL.y, bH.x, bH.y};
#pragma unroll
            for (int ii = 0; ii < 4; ii++)
#pragma unroll
                for (int jj = 0; jj < 4; jj++) {
                    u64 d = addx2(a2[ii], b2[jj]);          // a + eps - b
                    d &= 0x7FFFFFFF7FFFFFFFull;             // packed |.|
                    acc2[ii * 4 + jj] = addx2(acc2[ii * 4 + jj], d);
                }
        }
        if (ch < 3) STORECHUNK((ch + 1) & 1);
        __syncthreads();
    }

    float* dhalf = g_D + (size_t)cs * N * MAXC;
#pragma unroll
    for (int ii = 0; ii < 4; ii++) {
        int ti = ti0 + ty * 4 + ii;
        if (ti >= cnt) continue;
        float o[4];
#pragma unroll
        for (int jj = 0; jj < 4; jj++) {
            u64 a = acc2[ii * 4 + jj];
            float lo = __uint_as_float((unsigned)(a & 0xFFFFFFFFull));
            float hi = __uint_as_float((unsigned)(a >> 32));
            int tj = tj0 + tx * 4 + jj;
            o[jj] = (ti == tj) ? finf() : (lo + hi);
        }
        // junk columns beyond cnt never read by topk
        *(float4*)(dhalf + (size_t)list[ti] * MAXC + tj0 + tx * 4) =
            make_float4(o[0], o[1], o[2], o[3]);
    }
}

// ---------------------------------------------------------------------------
// Kernel 2: fused top-K + neighbor MSE + CE + final reduction (last block).
// One warp per row. Packed keys + argmin-2 rounds; lanes 0..19 resolve their
// own neighbor index (parallel L2 loads) before the gather.
// ---------------------------------------------------------------------------
__global__ __launch_bounds__(256, 2)
void topk_loss_kernel(const float* __restrict__ feat,
                      const float* __restrict__ scores,
                      const int* __restrict__ target,
                      float* __restrict__ out) {
    __shared__ float s_part[8];
    __shared__ bool  s_last;

    int warp = threadIdx.x >> 5;
    int lane = threadIdx.x & 31;
    int i = blockIdx.x * 8 + warp;

    int cls = target[i];
    int cnt = min(g_cntC[cls], MAXC);
    const int* order = g_orderC + cls * MAXC;
    int m = min(cnt - 1, KSEL);

    float rowloss = 0.f;
    if (m > 0) {
        const float* d0 = g_D + (size_t)i * MAXC;
        const float* d1 = g_D + (size_t)(N + i) * MAXC;

        // packed keys: high 23 bits of distance | 9-bit position
        unsigned v[12];
#pragma unroll
        for (int s = 0; s < 12; s++) {
            int p = s * 32 + lane;
            if (p < cnt) {
                float d = d0[p] + d1[p];
                v[s] = (__float_as_uint(d) & 0xFFFFFE00u) | (unsigned)p;
            } else {
                v[s] = 0xFFFFFFFFu;
            }
        }

        unsigned mypos = 0;
#pragma unroll
        for (int r = 0; r < 10; r++) {
            // local two smallest of 12 slots
            unsigned k1 = 0xFFFFFFFFu, k2 = 0xFFFFFFFFu;
#pragma unroll
            for (int s = 0; s < 12; s++) {
                unsigned xv = v[s];
                unsigned nk2 = min(k2, max(k1, xv));
                k1 = min(k1, xv);
                k2 = nk2;
            }
            // warp-wide two smallest
#pragma unroll
            for (int o = 16; o > 0; o >>= 1) {
                unsigned p1 = __shfl_down_sync(0xffffffffu, k1, o);
                unsigned p2 = __shfl_down_sync(0xffffffffu, k2, o);
                unsigned hi = max(k1, p1);
                k1 = min(k1, p1);
                k2 = min(hi, min(k2, p2));
            }
            unsigned w1 = __shfl_sync(0xffffffffu, k1, 0);
            unsigned w2 = __shfl_sync(0xffffffffu, k2, 0);
            if (lane == 2 * r)     mypos = w1 & 511u;
            if (lane == 2 * r + 1) mypos = w2 & 511u;
#pragma unroll
            for (int s = 0; s < 12; s++) {
                if (v[s] == w1 || v[s] == w2) v[s] = 0xFFFFFFFFu;
            }
        }

        // resolve neighbor original index per lane (20 parallel loads)
        unsigned cp = min(mypos, (unsigned)(MAXC - 1));
        int myj = order[cp];

        // MSE gather: lane owns 8 channels; pre-resolved j broadcast per k.
        float inv_m = 1.0f / (float)m;
        const float* xi = feat + (size_t)i * C + lane * 8;
        float4 x0 = *(const float4*)(xi);
        float4 x1 = *(const float4*)(xi + 4);
        float acc = 0.f;
#pragma unroll
        for (int k = 0; k < KSEL; k++) {
            bool valid = (k < m);
            int j = __shfl_sync(0xffffffffu, myj, k);
            const float* xj = feat + (size_t)j * C + lane * 8;
            float4 a0 = *(const float4*)(xj);
            float4 a1 = *(const float4*)(xj + 4);
            float s = 0.f, d;
            d = x0.x - a0.x * inv_m; s += d * d;
            d = x0.y - a0.y * inv_m; s += d * d;
            d = x0.z - a0.z * inv_m; s += d * d;
            d = x0.w - a0.w * inv_m; s += d * d;
            d = x1.x - a1.x * inv_m; s += d * d;
            d = x1.y - a1.y * inv_m; s += d * d;
            d = x1.z - a1.z * inv_m; s += d * d;
            d = x1.w - a1.w * inv_m; s += d * d;
            acc += valid ? s : 0.f;
        }
#pragma unroll
        for (int o = 16; o > 0; o >>= 1)
            acc += __shfl_down_sync(0xffffffffu, acc, o);
        rowloss = acc;
    }

    // per-row CE (lane 0), combine with lam term
    if (lane == 0) {
        float4 s0 = *(const float4*)(scores + (size_t)i * NCLS);
        float4 s1 = *(const float4*)(scores + (size_t)i * NCLS + 4);
        float sv[8] = {s0.x, s0.y, s0.z, s0.w, s1.x, s1.y, s1.z, s1.w};
        float mx = sv[0];
#pragma unroll
        for (int c = 1; c < 8; c++) mx = fmaxf(mx, sv[c]);
        float se = 0.f;
#pragma unroll
        for (int c = 0; c < 8; c++) se += __expf(sv[c] - mx);
        float ce = (mx + __logf(se)) - sv[cls];
        s_part[warp] = ce * (1.0f / (float)N) + 25.0f * rowloss;  // LAM*0.5 = 25
    }
    __syncthreads();

    if (threadIdx.x == 0) {
        float p = 0.f;
#pragma unroll
        for (int w = 0; w < 8; w++) p += s_part[w];
        g_partial[blockIdx.x] = p;
        __threadfence();
        unsigned int done = atomicAdd(&g_counter, 1u);
        s_last = (done == 255u);
    }
    __syncthreads();

    if (s_last) {
        __shared__ float sred[256];
        int t = threadIdx.x;
        sred[t] = g_partial[t];
        __syncthreads();
        for (int o = 128; o > 0; o >>= 1) {
            if (t < o) sred[t] += sred[t + o];
            __syncthreads();
        }
        if (t == 0) out[0] = sred[0];
    }
}

// ---------------------------------------------------------------------------
extern "C" void kernel_launch(void* const* d_in, const int* in_sizes, int n_in,
                              void* d_out, int out_size) {
    const float* feature = (const float*)d_in[0];   // [2048, 256]
    const float* scores  = (const float*)d_in[1];   // [2048, 8]
    const int*   target  = (const int*)d_in[2];     // [2048]
    float* out = (float*)d_out;

    dist_kernel<<<576, 256>>>(feature, target);
    topk_loss_kernel<<<N / 8, 256>>>(feature, scores, target, out);
}